// round 7
// baseline (speedup 1.0000x reference)
#include <cuda_runtime.h>
#include <math.h>

#define Gn 128
typedef unsigned long long U64;

static const long long O_XOUT=0LL, O_Z=33554432LL, O_ZHAT=50331648LL, O_SURP=67108864LL,
 O_KC=67371008LL, O_VP=84148224LL, O_GATE=100925440LL, O_QN=101187584LL,
 O_VC=117964800LL, O_WN=134742016LL, O_S4=135004160LL;

__device__ __forceinline__ void f2fma(U64& d, U64 a, U64 b){
    asm("fma.rn.f32x2 %0, %1, %2, %0;" : "+l"(d) : "l"(a), "l"(b));
}
__device__ __forceinline__ void f2add(U64& d, U64 a){
    asm("add.rn.f32x2 %0, %0, %1;" : "+l"(d) : "l"(a));
}
__device__ __forceinline__ U64 dup2(float a){
    U64 r; asm("mov.b64 %0, {%1, %1};" : "=l"(r) : "f"(a)); return r;
}
__device__ __forceinline__ float4 pk4(U64 p0, U64 p1){
    float4 v;
    asm("mov.b64 {%0, %1}, %2;" : "=f"(v.x), "=f"(v.y) : "l"(p0));
    asm("mov.b64 {%0, %1}, %2;" : "=f"(v.z), "=f"(v.w) : "l"(p1));
    return v;
}
__device__ __forceinline__ void cpa16(float* dst, const float* src){
    unsigned d = (unsigned)__cvta_generic_to_shared(dst);
    asm volatile("cp.async.ca.shared.global [%0], [%1], 16;" :: "r"(d), "l"(src) : "memory");
}
__device__ __forceinline__ void cpa4(float* dst, const float* src){
    unsigned d = (unsigned)__cvta_generic_to_shared(dst);
    asm volatile("cp.async.ca.shared.global [%0], [%1], 4;" :: "r"(d), "l"(src) : "memory");
}
__device__ __forceinline__ void cpcommit(){ asm volatile("cp.async.commit_group;" ::: "memory"); }
__device__ __forceinline__ void cpwait0(){ asm volatile("cp.async.wait_group 0;" ::: "memory"); }
__device__ __forceinline__ void fz2(U64* c){
#pragma unroll
    for (int i=0;i<32;i++) c[i]=0ULL;
}
__device__ __forceinline__ void redK2(U64* c){
#pragma unroll
    for (int i=0;i<32;i++) f2add(c[i], __shfl_xor_sync(0xffffffffu, c[i], 16));
}
__device__ __forceinline__ void redK4(U64* c){
#pragma unroll
    for (int i=0;i<32;i++){
        f2add(c[i], __shfl_xor_sync(0xffffffffu, c[i], 8));
        f2add(c[i], __shfl_xor_sync(0xffffffffu, c[i], 16));
    }
}

// ---- inner loops: warp = 8 tokens (ty); lanes split K and columns ----
__device__ __forceinline__ void innU64(const float* As, int kbase, const float* wb, int rbase,
                                       U64 c2[][4], int ty, int tx8){
    float4 a4[8];
#pragma unroll
    for (int tt=0;tt<8;tt++) a4[tt] = *(const float4*)&As[(ty*8+tt)*132 + kbase];
#pragma unroll
    for (int r=0;r<4;r++){
        ulonglong2 w0 = *(const ulonglong2*)&wb[(rbase+r)*64 + tx8*4];
        ulonglong2 w1 = *(const ulonglong2*)&wb[(rbase+r)*64 + 32 + tx8*4];
#pragma unroll
        for (int tt=0;tt<8;tt++){
            U64 a = dup2(((const float*)&a4[tt])[r]);
            f2fma(c2[tt][0],a,w0.x); f2fma(c2[tt][1],a,w0.y);
            f2fma(c2[tt][2],a,w1.x); f2fma(c2[tt][3],a,w1.y);
        }
    }
}
__device__ __forceinline__ void innU128(const float* As, int kbase, const float* wb, int rbase,
                                        U64 c2[][4], int ty, int tx){
#pragma unroll
    for (int rp=0;rp<2;rp++){
        float2 a2[8];
#pragma unroll
        for (int tt=0;tt<8;tt++) a2[tt] = *(const float2*)&As[(ty*8+tt)*132 + kbase + rp*2];
#pragma unroll
        for (int rr=0;rr<2;rr++){
            int r = rp*2+rr;
            ulonglong2 w0 = *(const ulonglong2*)&wb[(rbase+r)*128 + tx*4];
            ulonglong2 w1 = *(const ulonglong2*)&wb[(rbase+r)*128 + 64 + tx*4];
#pragma unroll
            for (int tt=0;tt<8;tt++){
                U64 a = dup2(rr ? a2[tt].y : a2[tt].x);
                f2fma(c2[tt][0],a,w0.x); f2fma(c2[tt][1],a,w0.y);
                f2fma(c2[tt][2],a,w1.x); f2fma(c2[tt][3],a,w1.y);
            }
        }
    }
}

// ---- GEMM drivers with cp.async double-buffered staging ----
__device__ __forceinline__ void g64(const float* As, const float* __restrict__ W, long wst, int K,
                                    float* wsm, U64 c2[][4], int ty, int kh2, int tx8, int tid){
    int K4=K>>2, nc=K>>4;
    int rr=tid>>4, c4=(tid&15)*4;
    cpa16(&wsm[rr*64+c4], &W[(size_t)((rr>>2)*K4 + (rr&3))*wst + c4]); cpcommit();
    for (int c=0;c<nc;c++){
        cpwait0(); __syncthreads();
        if (c+1<nc){
            cpa16(&wsm[((c+1)&1)*1024 + rr*64+c4],
                  &W[(size_t)((rr>>2)*K4 + (c+1)*4 + (rr&3))*wst + c4]); cpcommit();
        }
        innU64(As, kh2*K4 + c*4, wsm + (c&1)*1024, kh2*4, c2, ty, tx8);
    }
    __syncthreads();
}
__device__ __forceinline__ void g64T(const float* As, const float* __restrict__ S, int slots,
                                     float* wsm, U64 c2[][4], int ty, int kh2, int tx8, int tid){
    int s = tid&63, g4 = tid>>6;
    for (int c=0;c<4;c++){
        float4 v = make_float4(0.f,0.f,0.f,0.f);
        if (s < slots) v = *(const float4*)&S[s*64 + g4*16 + c*4];
        __syncthreads();
        wsm[(g4*4+0)*64+s]=v.x; wsm[(g4*4+1)*64+s]=v.y;
        wsm[(g4*4+2)*64+s]=v.z; wsm[(g4*4+3)*64+s]=v.w;
        __syncthreads();
        innU64(As, kh2*16 + c*4, wsm, kh2*4, c2, ty, tx8);
    }
    __syncthreads();
}
template<bool UA>
__device__ __forceinline__ void g128(const float* As, const float* __restrict__ W, long wst, int K,
                                     float* wsm, U64 c2[][4], int ty, int kh, int tx, int tid){
    int K2=K>>1, nc=K>>3;
    int rr8=tid>>5, c48=(tid&31)*4;
#define STAGE128(cc, buf) do { \
    if (UA){ \
        for (int j=0;j<4;j++){ int flat=tid+256*j; int r_=flat>>7, col_=flat&127; \
            cpa4(&(buf)[r_*128+col_], &W[(size_t)((r_>>2)*K2 + (cc)*4 + (r_&3))*wst + col_]); } \
    } else { \
        cpa16(&(buf)[rr8*128+c48], &W[(size_t)((rr8>>2)*K2 + (cc)*4 + (rr8&3))*wst + c48]); \
    } \
    cpcommit(); } while(0)
    STAGE128(0, wsm);
    for (int c=0;c<nc;c++){
        cpwait0(); __syncthreads();
        if (c+1<nc) STAGE128(c+1, wsm + ((c+1)&1)*1024);
        innU128(As, kh*K2 + c*4, wsm + (c&1)*1024, kh*4, c2, ty, tx);
    }
    __syncthreads();
#undef STAGE128
}

// ---- epilogues ----
__device__ __forceinline__ void eps64(U64 c2[][4], float* buf, const float* bias,
                                      int ty, int kh2, int tx8){
    if (kh2 >= 2) return;
    int col = kh2*32 + tx8*4;
    float4 bv = bias ? *(const float4*)&bias[col] : make_float4(0.f,0.f,0.f,0.f);
#pragma unroll
    for (int tt=0;tt<8;tt++){
        float4 v = pk4(c2[tt][kh2*2], c2[tt][kh2*2+1]);
        v.x+=bv.x; v.y+=bv.y; v.z+=bv.z; v.w+=bv.w;
        *(float4*)&buf[(ty*8+tt)*132 + col] = v;
    }
}
__device__ __forceinline__ void epxs(U64 c2[][4], float* xs, int ty, int kh, int tx){
    int col = kh*64 + tx*4;
#pragma unroll
    for (int tt=0;tt<8;tt++){
        float* p = &xs[(ty*8+tt)*132 + col];
        float4 x = *(float4*)p;
        float4 v = pk4(c2[tt][kh*2], c2[tt][kh*2+1]);
        x.x+=v.x; x.y+=v.y; x.z+=v.z; x.w+=v.w;
        *(float4*)p = x;
    }
}

template <int SLOTS>
__device__ __forceinline__ void softmax_q(float* buf, int tok, int jq){
    const int nS = SLOTS/4;
    float l[nS]; float m = -1e30f;
#pragma unroll
    for (int i=0;i<nS;i++){ l[i] = buf[tok*132 + jq*nS + i]*0.125f; m = fmaxf(m, l[i]); }
    m = fmaxf(m, __shfl_xor_sync(0xffffffffu, m, 1));
    m = fmaxf(m, __shfl_xor_sync(0xffffffffu, m, 2));
    float s = 0.f;
#pragma unroll
    for (int i=0;i<nS;i++){ l[i]=expf(l[i]-m); s+=l[i]; }
    s += __shfl_xor_sync(0xffffffffu, s, 1);
    s += __shfl_xor_sync(0xffffffffu, s, 2);
    float inv = 1.f/s;
#pragma unroll
    for (int i=0;i<nS;i++) buf[tok*132 + jq*nS + i] = l[i]*inv;
}

__global__ void __launch_bounds__(256, 2)
ccg_kernel(
    const float* __restrict__ x_col, const float* __restrict__ pm_state,
    const float* __restrict__ em_state, const float* __restrict__ z_hat_prev,
    const float* __restrict__ ffn_norm_w, const float* __restrict__ ffn_norm_b,
    const float* __restrict__ ffn_up_w, const float* __restrict__ ffn_up_b,
    const float* __restrict__ ffn_down_w, const float* __restrict__ ffn_down_b,
    const float* __restrict__ pm_up_w, const float* __restrict__ pm_up_b,
    const float* __restrict__ pm_down_w, const float* __restrict__ pm_down_b,
    const float* __restrict__ em_up_w, const float* __restrict__ em_up_b,
    const float* __restrict__ em_down_w, const float* __restrict__ em_down_b,
    const float* __restrict__ post_w, const float* __restrict__ post_b,
    const float* __restrict__ enc_w, const float* __restrict__ enc_b,
    const float* __restrict__ pred_w, const float* __restrict__ pred_b,
    const float* __restrict__ gain_w, const float* __restrict__ gain_b,
    float* __restrict__ out)
{
    extern __shared__ float smf[];
    float* xs  = smf;               // 64 x 132 residual
    float* hs  = xs + 64*132;       // 64 x 132 logits/z/gain/gelu/post-k
    float* bC  = hs + 64*132;       // 64 x 132 q/apply/delta/h
    float* wsm = bC + 64*132;       // 2 x 1024 weight staging

    const int tid = threadIdx.x;
    const int lane = tid & 31, ty = tid >> 5;
    const int kh = lane >> 4, tx = lane & 15;
    const int kh2 = lane >> 3, tx8 = lane & 7;
    const int tok = tid >> 2, jq = tid & 3;
    const int g = blockIdx.y, t0 = blockIdx.x*64;
    const int bs = t0 >> 9, bidx = g >> 4;

    U64 c2[8][4];

#pragma unroll
    for (int jj=0;jj<8;jj++){
        int flat = tid + 256*jj, r = flat>>5, c4 = flat&31;
        *(float4*)&xs[r*132 + c4*4] =
            *(const float4*)&x_col[((size_t)(t0+r)*Gn + g)*128 + c4*4];
    }

    // ===== pm stage =====
    fz2(&c2[0][0]);
    g64(xs, pm_up_w + (size_t)g*8192, 64, 128, wsm, c2, ty, kh2, tx8, tid);
    redK4(&c2[0][0]);
    eps64(c2, bC, pm_up_b + g*64, ty, kh2, tx8);

    const float* Spm = pm_state + (size_t)((bs*8 + bidx)*16)*64;
    fz2(&c2[0][0]);
    g64T(bC, Spm, 16, wsm, c2, ty, kh2, tx8, tid);
    redK4(&c2[0][0]);
    eps64(c2, hs, (const float*)0, ty, kh2, tx8);
    __syncthreads();
    softmax_q<16>(hs, tok, jq);
    __syncthreads();

    fz2(&c2[0][0]);
    g64(hs, Spm, 64, 16, wsm, c2, ty, kh2, tx8, tid);
    redK4(&c2[0][0]);
    eps64(c2, bC, (const float*)0, ty, kh2, tx8);

    fz2(&c2[0][0]);
    g128<false>(bC, pm_down_w + (size_t)g*8192, 128, 64, wsm, c2, ty, kh, tx, tid);
    redK2(&c2[0][0]);
    {   int col = kh*64 + tx*4;
        float4 bv = *(const float4*)&pm_down_b[g*128 + col];
#pragma unroll
        for (int tt=0;tt<8;tt++){
            float* p = &xs[(ty*8+tt)*132 + col];
            float4 x = *(float4*)p; float4 v = pk4(c2[tt][kh*2], c2[tt][kh*2+1]);
            x.x+=v.x+bv.x; x.y+=v.y+bv.y; x.z+=v.z+bv.z; x.w+=v.w+bv.w;
            *(float4*)p = x;
        }
    }

    // ===== em stage =====
    fz2(&c2[0][0]);
    g64(xs, em_up_w + (size_t)g*8192, 64, 128, wsm, c2, ty, kh2, tx8, tid);
    redK4(&c2[0][0]);
    eps64(c2, bC, em_up_b + g*64, ty, kh2, tx8);

    const float* Sem = em_state + (size_t)((bs*8 + bidx)*64)*64;
    fz2(&c2[0][0]);
    g64T(bC, Sem, 64, wsm, c2, ty, kh2, tx8, tid);
    redK4(&c2[0][0]);
    eps64(c2, hs, (const float*)0, ty, kh2, tx8);
    __syncthreads();
    softmax_q<64>(hs, tok, jq);
    __syncthreads();

    fz2(&c2[0][0]);
    g64(hs, Sem, 64, 64, wsm, c2, ty, kh2, tx8, tid);
    redK4(&c2[0][0]);
    eps64(c2, bC, (const float*)0, ty, kh2, tx8);

    fz2(&c2[0][0]);
    g128<false>(bC, em_down_w + (size_t)g*8192, 128, 64, wsm, c2, ty, kh, tx, tid);
    redK2(&c2[0][0]);
    {   int col = kh*64 + tx*4;
        float4 bv = *(const float4*)&em_down_b[g*128 + col];
#pragma unroll
        for (int tt=0;tt<8;tt++){
            float* p = &xs[(ty*8+tt)*132 + col];
            float4 x = *(float4*)p; float4 v = pk4(c2[tt][kh*2], c2[tt][kh*2+1]);
            x.x+=v.x+bv.x; x.y+=v.y+bv.y; x.z+=v.z+bv.z; x.w+=v.w+bv.w;
            *(float4*)p = x;
        }
    }

    // ===== enc / delta / surprise =====
    fz2(&c2[0][0]);
    g64(xs, enc_w + (size_t)g*8192, 64, 128, wsm, c2, ty, kh2, tx8, tid);
    redK4(&c2[0][0]);
    if (kh2 == 0){
        float ss[8];
        float4 b0 = *(const float4*)&enc_b[g*64 + tx8*4];
        float4 b1 = *(const float4*)&enc_b[g*64 + 32 + tx8*4];
#pragma unroll
        for (int tt=0;tt<8;tt++){
            int t = ty*8+tt; size_t tg = t0+t;
            float4 z0 = pk4(c2[tt][0], c2[tt][1]);
            float4 z1 = pk4(c2[tt][2], c2[tt][3]);
            z0.x+=b0.x; z0.y+=b0.y; z0.z+=b0.z; z0.w+=b0.w;
            z1.x+=b1.x; z1.y+=b1.y; z1.z+=b1.z; z1.w+=b1.w;
            float4 h0 = *(const float4*)&z_hat_prev[(tg*Gn+g)*64 + tx8*4];
            float4 h1 = *(const float4*)&z_hat_prev[(tg*Gn+g)*64 + 32 + tx8*4];
            float4 d0 = make_float4(z0.x-h0.x, z0.y-h0.y, z0.z-h0.z, z0.w-h0.w);
            float4 d1 = make_float4(z1.x-h1.x, z1.y-h1.y, z1.z-h1.z, z1.w-h1.w);
            ss[tt] = d0.x*d0.x+d0.y*d0.y+d0.z*d0.z+d0.w*d0.w
                   + d1.x*d1.x+d1.y*d1.y+d1.z*d1.z+d1.w*d1.w;
            *(float4*)&hs[t*132 + tx8*4] = z0;      *(float4*)&hs[t*132 + 32 + tx8*4] = z1;
            *(float4*)&bC[t*132 + tx8*4] = d0;      *(float4*)&bC[t*132 + 32 + tx8*4] = d1;
            *(float4*)&out[O_Z + (tg*Gn+g)*64 + tx8*4] = z0;
            *(float4*)&out[O_Z + (tg*Gn+g)*64 + 32 + tx8*4] = z1;
        }
#pragma unroll
        for (int tt=0;tt<8;tt++){
            ss[tt] += __shfl_xor_sync(0x000000ffu, ss[tt], 1);
            ss[tt] += __shfl_xor_sync(0x000000ffu, ss[tt], 2);
            ss[tt] += __shfl_xor_sync(0x000000ffu, ss[tt], 4);
        }
        if (tx8 == 0){
#pragma unroll
            for (int tt=0;tt<8;tt++){
                size_t tg = t0 + ty*8 + tt;
                float s = sqrtf(ss[tt]);
                out[O_SURP + tg*Gn + g] = s;
                out[O_S4 + tg*Gn + g] = s;
                out[O_GATE + tg*Gn + g] = fminf(s, 1.f);
            }
        }
    }
    __syncthreads();

    // ===== z_hat (z in hs) =====
    fz2(&c2[0][0]);
    g64(hs, pred_w + (size_t)g*4096, 64, 64, wsm, c2, ty, kh2, tx8, tid);
    redK4(&c2[0][0]);
    if (kh2 < 2){
        int col = kh2*32 + tx8*4;
        float4 bv = *(const float4*)&pred_b[g*64 + col];
#pragma unroll
        for (int tt=0;tt<8;tt++){
            size_t tg = t0 + ty*8 + tt;
            float4 v = pk4(c2[tt][kh2*2], c2[tt][kh2*2+1]);
            v.x+=bv.x; v.y+=bv.y; v.z+=bv.z; v.w+=bv.w;
            *(float4*)&out[O_ZHAT + (tg*Gn+g)*64 + col] = v;
        }
    }

    // ===== gain (delta in bC) -> hs =====
    fz2(&c2[0][0]);
    g128<false>(bC, gain_w + (size_t)g*8192, 128, 64, wsm, c2, ty, kh, tx, tid);
    redK2(&c2[0][0]);
    {   int col = kh*64 + tx*4;
        float4 bv = *(const float4*)&gain_b[g*128 + col];
#pragma unroll
        for (int tt=0;tt<8;tt++){
            float4 v = pk4(c2[tt][kh*2], c2[tt][kh*2+1]);
            float4 o;
            o.x = 1.f + 0.1f*tanhf(v.x+bv.x); o.y = 1.f + 0.1f*tanhf(v.y+bv.y);
            o.z = 1.f + 0.1f*tanhf(v.z+bv.z); o.w = 1.f + 0.1f*tanhf(v.w+bv.w);
            *(float4*)&hs[(ty*8+tt)*132 + col] = o;
        }
    }
    __syncthreads();

    // ===== layernorm * gain -> bC =====
    {
        float s=0.f, sq=0.f; float4 xv[8];
#pragma unroll
        for (int u=0;u<8;u++){
            xv[u] = *(const float4*)&xs[tok*132 + jq*32 + u*4];
            s  += xv[u].x+xv[u].y+xv[u].z+xv[u].w;
            sq += xv[u].x*xv[u].x+xv[u].y*xv[u].y+xv[u].z*xv[u].z+xv[u].w*xv[u].w;
        }
        s  += __shfl_xor_sync(0xffffffffu, s, 1);
        s  += __shfl_xor_sync(0xffffffffu, s, 2);
        sq += __shfl_xor_sync(0xffffffffu, sq, 1);
        sq += __shfl_xor_sync(0xffffffffu, sq, 2);
        float mu = s*(1.f/128.f);
        float rstd = rsqrtf(sq*(1.f/128.f) - mu*mu + 1e-5f);
#pragma unroll
        for (int u=0;u<8;u++){
            int cb = jq*32 + u*4;
            float4 w4 = *(const float4*)&ffn_norm_w[g*128 + cb];
            float4 b4 = *(const float4*)&ffn_norm_b[g*128 + cb];
            float4 g4 = *(const float4*)&hs[tok*132 + cb];
            float4 h4;
            h4.x = ((xv[u].x-mu)*rstd*w4.x + b4.x)*g4.x;
            h4.y = ((xv[u].y-mu)*rstd*w4.y + b4.y)*g4.y;
            h4.z = ((xv[u].z-mu)*rstd*w4.z + b4.z)*g4.z;
            h4.w = ((xv[u].w-mu)*rstd*w4.w + b4.w)*g4.w;
            *(float4*)&bC[tok*132 + cb] = h4;
        }
    }

    // ===== FFN: h in bC; gelu -> hs; down accumulates into xs =====
    for (int ch=0; ch<4; ch++){
        fz2(&c2[0][0]);
        g128<false>(bC, ffn_up_w + (size_t)g*65536 + ch*128, 512, 128, wsm, c2, ty, kh, tx, tid);
        redK2(&c2[0][0]);
        {   int col = kh*64 + tx*4;
            float4 bv = *(const float4*)&ffn_up_b[g*512 + ch*128 + col];
#pragma unroll
            for (int tt=0;tt<8;tt++){
                float4 v = pk4(c2[tt][kh*2], c2[tt][kh*2+1]);
                float4 o;
                float u0=v.x+bv.x, u1=v.y+bv.y, u2=v.z+bv.z, u3=v.w+bv.w;
                o.x = 0.5f*u0*(1.f+erff(u0*0.70710678f));
                o.y = 0.5f*u1*(1.f+erff(u1*0.70710678f));
                o.z = 0.5f*u2*(1.f+erff(u2*0.70710678f));
                o.w = 0.5f*u3*(1.f+erff(u3*0.70710678f));
                *(float4*)&hs[(ty*8+tt)*132 + col] = o;
            }
        }
        fz2(&c2[0][0]);
        g128<false>(hs, ffn_down_w + (size_t)g*65536 + (size_t)ch*128*128, 128, 128, wsm, c2, ty, kh, tx, tid);
        redK2(&c2[0][0]);
        epxs(c2, xs, ty, kh, tx);
    }

    // ===== x_out: add down-bias, store =====
    {   int col = kh*64 + tx*4;
        float4 bv = *(const float4*)&ffn_down_b[g*128 + col];
#pragma unroll
        for (int tt=0;tt<8;tt++){
            int t = ty*8+tt; size_t tg = t0+t;
            float* p = &xs[t*132 + col];
            float4 x = *(float4*)p;
            x.x+=bv.x; x.y+=bv.y; x.z+=bv.z; x.w+=bv.w;
            *(float4*)p = x;
            *(float4*)&out[O_XOUT + (tg*Gn+g)*128 + col] = x;
        }
    }

    // ===== post projection: two 128-wide passes over xs =====
    for (int ph=0; ph<2; ph++){
        fz2(&c2[0][0]);
        g128<true>(xs, post_w + (size_t)g*32896 + ph*128, 257, 128, wsm, c2, ty, kh, tx, tid);
        redK2(&c2[0][0]);
        long long voff = ph ? O_VC : O_VP;
        long long noff = ph ? O_QN : O_KC;
        {   int col = kh*64 + tx*4;
            const float* pb = &post_b[(size_t)g*257 + ph*128 + col];   // stride 257: scalar loads (odd offset!)
            float4 bv = make_float4(pb[0], pb[1], pb[2], pb[3]);
#pragma unroll
            for (int tt=0;tt<8;tt++){
                size_t tg = t0 + ty*8 + tt;
                float4 v = pk4(c2[tt][kh*2], c2[tt][kh*2+1]);
                v.x+=bv.x; v.y+=bv.y; v.z+=bv.z; v.w+=bv.w;
                if (kh == 0) *(float4*)&hs[(ty*8+tt)*132 + tx*4] = v;
                else *(float4*)&out[voff + (tg*Gn+g)*64 + tx*4] = v;
            }
        }
        __syncthreads();
        {   // normalize hs rows (64 cols) -> out[noff]
            float4 r4[4]; float ss = 0.f;
#pragma unroll
            for (int u4=0;u4<4;u4++){
                r4[u4] = *(const float4*)&hs[tok*132 + jq*16 + u4*4];
                ss += r4[u4].x*r4[u4].x + r4[u4].y*r4[u4].y
                    + r4[u4].z*r4[u4].z + r4[u4].w*r4[u4].w;
            }
            ss += __shfl_xor_sync(0xffffffffu, ss, 1);
            ss += __shfl_xor_sync(0xffffffffu, ss, 2);
            float inv = 1.f/(sqrtf(ss) + 1e-6f);
            size_t tg = t0 + tok;
#pragma unroll
            for (int u4=0;u4<4;u4++){
                float4 v = make_float4(r4[u4].x*inv, r4[u4].y*inv, r4[u4].z*inv, r4[u4].w*inv);
                *(float4*)&out[noff + (tg*Gn+g)*64 + jq*16 + u4*4] = v;
            }
        }
        __syncthreads();
    }

    // ===== w_nov (proj column 256) =====
    if (tid < 128)
        wsm[tid] = post_w[(size_t)g*32896 + (size_t)tid*257 + 256];
    __syncthreads();
    {
        float acc = 0.f;
#pragma unroll
        for (int u=0;u<8;u++){
            float4 xv = *(const float4*)&xs[tok*132 + jq*32 + u*4];
            float4 wv = *(const float4*)&wsm[jq*32 + u*4];
            acc += xv.x*wv.x + xv.y*wv.y + xv.z*wv.z + xv.w*wv.w;
        }
        acc += __shfl_xor_sync(0xffffffffu, acc, 1);
        acc += __shfl_xor_sync(0xffffffffu, acc, 2);
        if (jq == 0){
            size_t tg = t0 + tok;
            float nv = acc + post_b[(size_t)g*257 + 256];
            out[O_WN + tg*Gn + g] = 1.f/(1.f + expf(-nv));
        }
    }
}

extern "C" void kernel_launch(void* const* d_in, const int* in_sizes, int n_in,
                              void* d_out, int out_size) {
    const float* x_col      = (const float*)d_in[0];
    const float* pm_state   = (const float*)d_in[1];
    const float* em_state   = (const float*)d_in[2];
    const float* z_hat_prev = (const float*)d_in[3];
    const float* ffn_norm_w = (const float*)d_in[4];
    const float* ffn_norm_b = (const float*)d_in[5];
    const float* ffn_up_w   = (const float*)d_in[6];
    const float* ffn_up_b   = (const float*)d_in[7];
    const float* ffn_down_w = (const float*)d_in[8];
    const float* ffn_down_b = (const float*)d_in[9];
    const float* pm_up_w    = (const float*)d_in[10];
    const float* pm_up_b    = (const float*)d_in[11];
    const float* pm_down_w  = (const float*)d_in[12];
    const float* pm_down_b  = (const float*)d_in[13];
    const float* em_up_w    = (const float*)d_in[14];
    const float* em_up_b    = (const float*)d_in[15];
    const float* em_down_w  = (const float*)d_in[16];
    const float* em_down_b  = (const float*)d_in[17];
    const float* post_w     = (const float*)d_in[18];
    const float* post_b     = (const float*)d_in[19];
    const float* enc_w      = (const float*)d_in[20];
    const float* enc_b      = (const float*)d_in[21];
    const float* pred_w     = (const float*)d_in[22];
    const float* pred_b     = (const float*)d_in[23];
    const float* gain_w     = (const float*)d_in[24];
    const float* gain_b     = (const float*)d_in[25];
    float* out = (float*)d_out;

    const int smem = (3*64*132 + 2*1024)*4;  // 109568 B
    cudaFuncSetAttribute(ccg_kernel, cudaFuncAttributeMaxDynamicSharedMemorySize, smem);
    dim3 grid(32, 128);
    ccg_kernel<<<grid, 256, smem>>>(
        x_col, pm_state, em_state, z_hat_prev,
        ffn_norm_w, ffn_norm_b, ffn_up_w, ffn_up_b, ffn_down_w, ffn_down_b,
        pm_up_w, pm_up_b, pm_down_w, pm_down_b,
        em_up_w, em_up_b, em_down_w, em_down_b,
        post_w, post_b, enc_w, enc_b, pred_w, pred_b, gain_w, gain_b,
        out);
}

// round 8
// speedup vs baseline: 1.3317x; 1.3317x over previous
#include <cuda_runtime.h>
#include <math.h>

#define Gn 128
typedef unsigned long long U64;

static const long long O_XOUT=0LL, O_Z=33554432LL, O_ZHAT=50331648LL, O_SURP=67108864LL,
 O_KC=67371008LL, O_VP=84148224LL, O_GATE=100925440LL, O_QN=101187584LL,
 O_VC=117964800LL, O_WN=134742016LL, O_S4=135004160LL;

__device__ __forceinline__ void f2fma(U64& d, U64 a, U64 b){
    asm("fma.rn.f32x2 %0, %1, %2, %0;" : "+l"(d) : "l"(a), "l"(b));
}
__device__ __forceinline__ void f2add(U64& d, U64 a){
    asm("add.rn.f32x2 %0, %0, %1;" : "+l"(d) : "l"(a));
}
__device__ __forceinline__ U64 dup2(float a){
    U64 r; asm("mov.b64 %0, {%1, %1};" : "=l"(r) : "f"(a)); return r;
}
__device__ __forceinline__ float4 pk4(U64 p0, U64 p1){
    float4 v;
    asm("mov.b64 {%0, %1}, %2;" : "=f"(v.x), "=f"(v.y) : "l"(p0));
    asm("mov.b64 {%0, %1}, %2;" : "=f"(v.z), "=f"(v.w) : "l"(p1));
    return v;
}
// constant-index select of accumulator pair — NO dynamic register-array indexing
__device__ __forceinline__ float4 pksel(const U64* c, int flag){
    U64 p0 = flag ? c[2] : c[0];
    U64 p1 = flag ? c[3] : c[1];
    return pk4(p0, p1);
}
__device__ __forceinline__ void cpa16(float* dst, const float* src){
    unsigned d = (unsigned)__cvta_generic_to_shared(dst);
    asm volatile("cp.async.ca.shared.global [%0], [%1], 16;" :: "r"(d), "l"(src) : "memory");
}
__device__ __forceinline__ void cpa4(float* dst, const float* src){
    unsigned d = (unsigned)__cvta_generic_to_shared(dst);
    asm volatile("cp.async.ca.shared.global [%0], [%1], 4;" :: "r"(d), "l"(src) : "memory");
}
__device__ __forceinline__ void cpcommit(){ asm volatile("cp.async.commit_group;" ::: "memory"); }
__device__ __forceinline__ void cpwait0(){ asm volatile("cp.async.wait_group 0;" ::: "memory"); }
__device__ __forceinline__ void fz2(U64* c){
#pragma unroll
    for (int i=0;i<32;i++) c[i]=0ULL;
}
__device__ __forceinline__ void redK2(U64* c){
#pragma unroll
    for (int i=0;i<32;i++) f2add(c[i], __shfl_xor_sync(0xffffffffu, c[i], 16));
}
__device__ __forceinline__ void redK4(U64* c){
#pragma unroll
    for (int i=0;i<32;i++){
        f2add(c[i], __shfl_xor_sync(0xffffffffu, c[i], 8));
        f2add(c[i], __shfl_xor_sync(0xffffffffu, c[i], 16));
    }
}

// ---- inner loops: warp = 8 tokens (ty); lanes split K and columns ----
__device__ __forceinline__ void innU64(const float* As, int kbase, const float* wb, int rbase,
                                       U64 c2[][4], int ty, int tx8){
    float4 a4[8];
#pragma unroll
    for (int tt=0;tt<8;tt++) a4[tt] = *(const float4*)&As[(ty*8+tt)*132 + kbase];
#pragma unroll
    for (int r=0;r<4;r++){
        ulonglong2 w0 = *(const ulonglong2*)&wb[(rbase+r)*64 + tx8*4];
        ulonglong2 w1 = *(const ulonglong2*)&wb[(rbase+r)*64 + 32 + tx8*4];
#pragma unroll
        for (int tt=0;tt<8;tt++){
            U64 a = dup2(((const float*)&a4[tt])[r]);
            f2fma(c2[tt][0],a,w0.x); f2fma(c2[tt][1],a,w0.y);
            f2fma(c2[tt][2],a,w1.x); f2fma(c2[tt][3],a,w1.y);
        }
    }
}
__device__ __forceinline__ void innU128(const float* As, int kbase, const float* wb, int rbase,
                                        U64 c2[][4], int ty, int tx){
#pragma unroll
    for (int rp=0;rp<2;rp++){
        float2 a2[8];
#pragma unroll
        for (int tt=0;tt<8;tt++) a2[tt] = *(const float2*)&As[(ty*8+tt)*132 + kbase + rp*2];
#pragma unroll
        for (int rr=0;rr<2;rr++){
            int r = rp*2+rr;
            ulonglong2 w0 = *(const ulonglong2*)&wb[(rbase+r)*128 + tx*4];
            ulonglong2 w1 = *(const ulonglong2*)&wb[(rbase+r)*128 + 64 + tx*4];
#pragma unroll
            for (int tt=0;tt<8;tt++){
                U64 a = dup2(rr ? a2[tt].y : a2[tt].x);
                f2fma(c2[tt][0],a,w0.x); f2fma(c2[tt][1],a,w0.y);
                f2fma(c2[tt][2],a,w1.x); f2fma(c2[tt][3],a,w1.y);
            }
        }
    }
}

// ---- GEMM drivers with cp.async double-buffered staging ----
__device__ __forceinline__ void g64(const float* As, const float* __restrict__ W, long wst, int K,
                                    float* wsm, U64 c2[][4], int ty, int kh2, int tx8, int tid){
    int K4=K>>2, nc=K>>4;
    int rr=tid>>4, c4=(tid&15)*4;
    cpa16(&wsm[rr*64+c4], &W[(size_t)((rr>>2)*K4 + (rr&3))*wst + c4]); cpcommit();
    for (int c=0;c<nc;c++){
        cpwait0(); __syncthreads();
        if (c+1<nc){
            cpa16(&wsm[((c+1)&1)*1024 + rr*64+c4],
                  &W[(size_t)((rr>>2)*K4 + (c+1)*4 + (rr&3))*wst + c4]); cpcommit();
        }
        innU64(As, kh2*K4 + c*4, wsm + (c&1)*1024, kh2*4, c2, ty, tx8);
    }
    __syncthreads();
}
__device__ __forceinline__ void g64T(const float* As, const float* __restrict__ S, int slots,
                                     float* wsm, U64 c2[][4], int ty, int kh2, int tx8, int tid){
    int s = tid&63, g4 = tid>>6;
    for (int c=0;c<4;c++){
        float4 v = make_float4(0.f,0.f,0.f,0.f);
        if (s < slots) v = *(const float4*)&S[s*64 + g4*16 + c*4];
        __syncthreads();
        wsm[(g4*4+0)*64+s]=v.x; wsm[(g4*4+1)*64+s]=v.y;
        wsm[(g4*4+2)*64+s]=v.z; wsm[(g4*4+3)*64+s]=v.w;
        __syncthreads();
        innU64(As, kh2*16 + c*4, wsm, kh2*4, c2, ty, tx8);
    }
    __syncthreads();
}
template<bool UA>
__device__ __forceinline__ void g128(const float* As, const float* __restrict__ W, long wst, int K,
                                     float* wsm, U64 c2[][4], int ty, int kh, int tx, int tid){
    int K2=K>>1, nc=K>>3;
    int rr8=tid>>5, c48=(tid&31)*4;
#define STAGE128(cc, buf) do { \
    if (UA){ \
        for (int j=0;j<4;j++){ int flat=tid+256*j; int r_=flat>>7, col_=flat&127; \
            cpa4(&(buf)[r_*128+col_], &W[(size_t)((r_>>2)*K2 + (cc)*4 + (r_&3))*wst + col_]); } \
    } else { \
        cpa16(&(buf)[rr8*128+c48], &W[(size_t)((rr8>>2)*K2 + (cc)*4 + (rr8&3))*wst + c48]); \
    } \
    cpcommit(); } while(0)
    STAGE128(0, wsm);
    for (int c=0;c<nc;c++){
        cpwait0(); __syncthreads();
        if (c+1<nc) STAGE128(c+1, wsm + ((c+1)&1)*1024);
        innU128(As, kh*K2 + c*4, wsm + (c&1)*1024, kh*4, c2, ty, tx);
    }
    __syncthreads();
#undef STAGE128
}

// ---- epilogues (all constant-index accumulator access) ----
__device__ __forceinline__ void eps64(U64 c2[][4], float* buf, const float* bias,
                                      int ty, int kh2, int tx8){
    if (kh2 >= 2) return;
    int col = kh2*32 + tx8*4;
    float4 bv = bias ? *(const float4*)&bias[col] : make_float4(0.f,0.f,0.f,0.f);
#pragma unroll
    for (int tt=0;tt<8;tt++){
        float4 v = pksel(c2[tt], kh2);
        v.x+=bv.x; v.y+=bv.y; v.z+=bv.z; v.w+=bv.w;
        *(float4*)&buf[(ty*8+tt)*132 + col] = v;
    }
}
__device__ __forceinline__ void epxs(U64 c2[][4], float* xs, int ty, int kh, int tx){
    int col = kh*64 + tx*4;
#pragma unroll
    for (int tt=0;tt<8;tt++){
        float* p = &xs[(ty*8+tt)*132 + col];
        float4 x = *(float4*)p;
        float4 v = pksel(c2[tt], kh);
        x.x+=v.x; x.y+=v.y; x.z+=v.z; x.w+=v.w;
        *(float4*)p = x;
    }
}

template <int SLOTS>
__device__ __forceinline__ void softmax_q(float* buf, int tok, int jq){
    const int nS = SLOTS/4;
    float l[nS]; float m = -1e30f;
#pragma unroll
    for (int i=0;i<nS;i++){ l[i] = buf[tok*132 + jq*nS + i]*0.125f; m = fmaxf(m, l[i]); }
    m = fmaxf(m, __shfl_xor_sync(0xffffffffu, m, 1));
    m = fmaxf(m, __shfl_xor_sync(0xffffffffu, m, 2));
    float s = 0.f;
#pragma unroll
    for (int i=0;i<nS;i++){ l[i]=expf(l[i]-m); s+=l[i]; }
    s += __shfl_xor_sync(0xffffffffu, s, 1);
    s += __shfl_xor_sync(0xffffffffu, s, 2);
    float inv = 1.f/s;
#pragma unroll
    for (int i=0;i<nS;i++) buf[tok*132 + jq*nS + i] = l[i]*inv;
}

__global__ void __launch_bounds__(256, 2)
ccg_kernel(
    const float* __restrict__ x_col, const float* __restrict__ pm_state,
    const float* __restrict__ em_state, const float* __restrict__ z_hat_prev,
    const float* __restrict__ ffn_norm_w, const float* __restrict__ ffn_norm_b,
    const float* __restrict__ ffn_up_w, const float* __restrict__ ffn_up_b,
    const float* __restrict__ ffn_down_w, const float* __restrict__ ffn_down_b,
    const float* __restrict__ pm_up_w, const float* __restrict__ pm_up_b,
    const float* __restrict__ pm_down_w, const float* __restrict__ pm_down_b,
    const float* __restrict__ em_up_w, const float* __restrict__ em_up_b,
    const float* __restrict__ em_down_w, const float* __restrict__ em_down_b,
    const float* __restrict__ post_w, const float* __restrict__ post_b,
    const float* __restrict__ enc_w, const float* __restrict__ enc_b,
    const float* __restrict__ pred_w, const float* __restrict__ pred_b,
    const float* __restrict__ gain_w, const float* __restrict__ gain_b,
    float* __restrict__ out)
{
    extern __shared__ float smf[];
    float* xs  = smf;               // 64 x 132 residual
    float* hs  = xs + 64*132;       // 64 x 132 logits/z/gain/gelu/post-k
    float* bC  = hs + 64*132;       // 64 x 132 q/apply/delta/h
    float* wsm = bC + 64*132;       // 2 x 1024 weight staging

    const int tid = threadIdx.x;
    const int lane = tid & 31, ty = tid >> 5;
    const int kh = lane >> 4, tx = lane & 15;
    const int kh2 = lane >> 3, tx8 = lane & 7;
    const int tok = tid >> 2, jq = tid & 3;
    const int g = blockIdx.y, t0 = blockIdx.x*64;
    const int bs = t0 >> 9, bidx = g >> 4;

    U64 c2[8][4];

#pragma unroll
    for (int jj=0;jj<8;jj++){
        int flat = tid + 256*jj, r = flat>>5, c4 = flat&31;
        *(float4*)&xs[r*132 + c4*4] =
            *(const float4*)&x_col[((size_t)(t0+r)*Gn + g)*128 + c4*4];
    }

    // ===== pm stage =====
    fz2(&c2[0][0]);
    g64(xs, pm_up_w + (size_t)g*8192, 64, 128, wsm, c2, ty, kh2, tx8, tid);
    redK4(&c2[0][0]);
    eps64(c2, bC, pm_up_b + g*64, ty, kh2, tx8);

    const float* Spm = pm_state + (size_t)((bs*8 + bidx)*16)*64;
    fz2(&c2[0][0]);
    g64T(bC, Spm, 16, wsm, c2, ty, kh2, tx8, tid);
    redK4(&c2[0][0]);
    eps64(c2, hs, (const float*)0, ty, kh2, tx8);
    __syncthreads();
    softmax_q<16>(hs, tok, jq);
    __syncthreads();

    fz2(&c2[0][0]);
    g64(hs, Spm, 64, 16, wsm, c2, ty, kh2, tx8, tid);
    redK4(&c2[0][0]);
    eps64(c2, bC, (const float*)0, ty, kh2, tx8);

    fz2(&c2[0][0]);
    g128<false>(bC, pm_down_w + (size_t)g*8192, 128, 64, wsm, c2, ty, kh, tx, tid);
    redK2(&c2[0][0]);
    {   int col = kh*64 + tx*4;
        float4 bv = *(const float4*)&pm_down_b[g*128 + col];
#pragma unroll
        for (int tt=0;tt<8;tt++){
            float* p = &xs[(ty*8+tt)*132 + col];
            float4 x = *(float4*)p; float4 v = pksel(c2[tt], kh);
            x.x+=v.x+bv.x; x.y+=v.y+bv.y; x.z+=v.z+bv.z; x.w+=v.w+bv.w;
            *(float4*)p = x;
        }
    }

    // ===== em stage =====
    fz2(&c2[0][0]);
    g64(xs, em_up_w + (size_t)g*8192, 64, 128, wsm, c2, ty, kh2, tx8, tid);
    redK4(&c2[0][0]);
    eps64(c2, bC, em_up_b + g*64, ty, kh2, tx8);

    const float* Sem = em_state + (size_t)((bs*8 + bidx)*64)*64;
    fz2(&c2[0][0]);
    g64T(bC, Sem, 64, wsm, c2, ty, kh2, tx8, tid);
    redK4(&c2[0][0]);
    eps64(c2, hs, (const float*)0, ty, kh2, tx8);
    __syncthreads();
    softmax_q<64>(hs, tok, jq);
    __syncthreads();

    fz2(&c2[0][0]);
    g64(hs, Sem, 64, 64, wsm, c2, ty, kh2, tx8, tid);
    redK4(&c2[0][0]);
    eps64(c2, bC, (const float*)0, ty, kh2, tx8);

    fz2(&c2[0][0]);
    g128<false>(bC, em_down_w + (size_t)g*8192, 128, 64, wsm, c2, ty, kh, tx, tid);
    redK2(&c2[0][0]);
    {   int col = kh*64 + tx*4;
        float4 bv = *(const float4*)&em_down_b[g*128 + col];
#pragma unroll
        for (int tt=0;tt<8;tt++){
            float* p = &xs[(ty*8+tt)*132 + col];
            float4 x = *(float4*)p; float4 v = pksel(c2[tt], kh);
            x.x+=v.x+bv.x; x.y+=v.y+bv.y; x.z+=v.z+bv.z; x.w+=v.w+bv.w;
            *(float4*)p = x;
        }
    }

    // ===== enc / delta / surprise =====
    fz2(&c2[0][0]);
    g64(xs, enc_w + (size_t)g*8192, 64, 128, wsm, c2, ty, kh2, tx8, tid);
    redK4(&c2[0][0]);
    if (kh2 == 0){
        float ss[8];
        float4 b0 = *(const float4*)&enc_b[g*64 + tx8*4];
        float4 b1 = *(const float4*)&enc_b[g*64 + 32 + tx8*4];
#pragma unroll
        for (int tt=0;tt<8;tt++){
            int t = ty*8+tt; size_t tg = t0+t;
            float4 z0 = pk4(c2[tt][0], c2[tt][1]);
            float4 z1 = pk4(c2[tt][2], c2[tt][3]);
            z0.x+=b0.x; z0.y+=b0.y; z0.z+=b0.z; z0.w+=b0.w;
            z1.x+=b1.x; z1.y+=b1.y; z1.z+=b1.z; z1.w+=b1.w;
            float4 h0 = *(const float4*)&z_hat_prev[(tg*Gn+g)*64 + tx8*4];
            float4 h1 = *(const float4*)&z_hat_prev[(tg*Gn+g)*64 + 32 + tx8*4];
            float4 d0 = make_float4(z0.x-h0.x, z0.y-h0.y, z0.z-h0.z, z0.w-h0.w);
            float4 d1 = make_float4(z1.x-h1.x, z1.y-h1.y, z1.z-h1.z, z1.w-h1.w);
            ss[tt] = d0.x*d0.x+d0.y*d0.y+d0.z*d0.z+d0.w*d0.w
                   + d1.x*d1.x+d1.y*d1.y+d1.z*d1.z+d1.w*d1.w;
            *(float4*)&hs[t*132 + tx8*4] = z0;      *(float4*)&hs[t*132 + 32 + tx8*4] = z1;
            *(float4*)&bC[t*132 + tx8*4] = d0;      *(float4*)&bC[t*132 + 32 + tx8*4] = d1;
            *(float4*)&out[O_Z + (tg*Gn+g)*64 + tx8*4] = z0;
            *(float4*)&out[O_Z + (tg*Gn+g)*64 + 32 + tx8*4] = z1;
        }
#pragma unroll
        for (int tt=0;tt<8;tt++){
            ss[tt] += __shfl_xor_sync(0x000000ffu, ss[tt], 1);
            ss[tt] += __shfl_xor_sync(0x000000ffu, ss[tt], 2);
            ss[tt] += __shfl_xor_sync(0x000000ffu, ss[tt], 4);
        }
        if (tx8 == 0){
#pragma unroll
            for (int tt=0;tt<8;tt++){
                size_t tg = t0 + ty*8 + tt;
                float s = sqrtf(ss[tt]);
                out[O_SURP + tg*Gn + g] = s;
                out[O_S4 + tg*Gn + g] = s;
                out[O_GATE + tg*Gn + g] = fminf(s, 1.f);
            }
        }
    }
    __syncthreads();

    // ===== z_hat (z in hs) =====
    fz2(&c2[0][0]);
    g64(hs, pred_w + (size_t)g*4096, 64, 64, wsm, c2, ty, kh2, tx8, tid);
    redK4(&c2[0][0]);
    if (kh2 < 2){
        int col = kh2*32 + tx8*4;
        float4 bv = *(const float4*)&pred_b[g*64 + col];
#pragma unroll
        for (int tt=0;tt<8;tt++){
            size_t tg = t0 + ty*8 + tt;
            float4 v = pksel(c2[tt], kh2);
            v.x+=bv.x; v.y+=bv.y; v.z+=bv.z; v.w+=bv.w;
            *(float4*)&out[O_ZHAT + (tg*Gn+g)*64 + col] = v;
        }
    }

    // ===== gain (delta in bC) -> hs =====
    fz2(&c2[0][0]);
    g128<false>(bC, gain_w + (size_t)g*8192, 128, 64, wsm, c2, ty, kh, tx, tid);
    redK2(&c2[0][0]);
    {   int col = kh*64 + tx*4;
        float4 bv = *(const float4*)&gain_b[g*128 + col];
#pragma unroll
        for (int tt=0;tt<8;tt++){
            float4 v = pksel(c2[tt], kh);
            float4 o;
            o.x = 1.f + 0.1f*tanhf(v.x+bv.x); o.y = 1.f + 0.1f*tanhf(v.y+bv.y);
            o.z = 1.f + 0.1f*tanhf(v.z+bv.z); o.w = 1.f + 0.1f*tanhf(v.w+bv.w);
            *(float4*)&hs[(ty*8+tt)*132 + col] = o;
        }
    }
    __syncthreads();

    // ===== layernorm * gain -> bC =====
    {
        float s=0.f, sq=0.f; float4 xv[8];
#pragma unroll
        for (int u=0;u<8;u++){
            xv[u] = *(const float4*)&xs[tok*132 + jq*32 + u*4];
            s  += xv[u].x+xv[u].y+xv[u].z+xv[u].w;
            sq += xv[u].x*xv[u].x+xv[u].y*xv[u].y+xv[u].z*xv[u].z+xv[u].w*xv[u].w;
        }
        s  += __shfl_xor_sync(0xffffffffu, s, 1);
        s  += __shfl_xor_sync(0xffffffffu, s, 2);
        sq += __shfl_xor_sync(0xffffffffu, sq, 1);
        sq += __shfl_xor_sync(0xffffffffu, sq, 2);
        float mu = s*(1.f/128.f);
        float rstd = rsqrtf(sq*(1.f/128.f) - mu*mu + 1e-5f);
#pragma unroll
        for (int u=0;u<8;u++){
            int cb = jq*32 + u*4;
            float4 w4 = *(const float4*)&ffn_norm_w[g*128 + cb];
            float4 b4 = *(const float4*)&ffn_norm_b[g*128 + cb];
            float4 g4 = *(const float4*)&hs[tok*132 + cb];
            float4 h4;
            h4.x = ((xv[u].x-mu)*rstd*w4.x + b4.x)*g4.x;
            h4.y = ((xv[u].y-mu)*rstd*w4.y + b4.y)*g4.y;
            h4.z = ((xv[u].z-mu)*rstd*w4.z + b4.z)*g4.z;
            h4.w = ((xv[u].w-mu)*rstd*w4.w + b4.w)*g4.w;
            *(float4*)&bC[tok*132 + cb] = h4;
        }
    }

    // ===== FFN: h in bC; gelu -> hs; down accumulates into xs =====
    for (int ch=0; ch<4; ch++){
        fz2(&c2[0][0]);
        g128<false>(bC, ffn_up_w + (size_t)g*65536 + ch*128, 512, 128, wsm, c2, ty, kh, tx, tid);
        redK2(&c2[0][0]);
        {   int col = kh*64 + tx*4;
            float4 bv = *(const float4*)&ffn_up_b[g*512 + ch*128 + col];
#pragma unroll
            for (int tt=0;tt<8;tt++){
                float4 v = pksel(c2[tt], kh);
                float4 o;
                float u0=v.x+bv.x, u1=v.y+bv.y, u2=v.z+bv.z, u3=v.w+bv.w;
                o.x = 0.5f*u0*(1.f+erff(u0*0.70710678f));
                o.y = 0.5f*u1*(1.f+erff(u1*0.70710678f));
                o.z = 0.5f*u2*(1.f+erff(u2*0.70710678f));
                o.w = 0.5f*u3*(1.f+erff(u3*0.70710678f));
                *(float4*)&hs[(ty*8+tt)*132 + col] = o;
            }
        }
        fz2(&c2[0][0]);
        g128<false>(hs, ffn_down_w + (size_t)g*65536 + (size_t)ch*128*128, 128, 128, wsm, c2, ty, kh, tx, tid);
        redK2(&c2[0][0]);
        epxs(c2, xs, ty, kh, tx);
    }

    // ===== x_out: add down-bias, store =====
    {   int col = kh*64 + tx*4;
        float4 bv = *(const float4*)&ffn_down_b[g*128 + col];
#pragma unroll
        for (int tt=0;tt<8;tt++){
            int t = ty*8+tt; size_t tg = t0+t;
            float* p = &xs[t*132 + col];
            float4 x = *(float4*)p;
            x.x+=bv.x; x.y+=bv.y; x.z+=bv.z; x.w+=bv.w;
            *(float4*)p = x;
            *(float4*)&out[O_XOUT + (tg*Gn+g)*128 + col] = x;
        }
    }

    // ===== post projection: two 128-wide passes over xs =====
    for (int ph=0; ph<2; ph++){
        fz2(&c2[0][0]);
        g128<true>(xs, post_w + (size_t)g*32896 + ph*128, 257, 128, wsm, c2, ty, kh, tx, tid);
        redK2(&c2[0][0]);
        long long voff = ph ? O_VC : O_VP;
        long long noff = ph ? O_QN : O_KC;
        {   int col = kh*64 + tx*4;
            const float* pb = &post_b[(size_t)g*257 + ph*128 + col];   // stride 257: scalar loads
            float4 bv = make_float4(pb[0], pb[1], pb[2], pb[3]);
#pragma unroll
            for (int tt=0;tt<8;tt++){
                size_t tg = t0 + ty*8 + tt;
                float4 v = pksel(c2[tt], kh);
                v.x+=bv.x; v.y+=bv.y; v.z+=bv.z; v.w+=bv.w;
                if (kh == 0) *(float4*)&hs[(ty*8+tt)*132 + tx*4] = v;
                else *(float4*)&out[voff + (tg*Gn+g)*64 + tx*4] = v;
            }
        }
        __syncthreads();
        {   // normalize hs rows (64 cols) -> out[noff]
            float4 r4[4]; float ss = 0.f;
#pragma unroll
            for (int u4=0;u4<4;u4++){
                r4[u4] = *(const float4*)&hs[tok*132 + jq*16 + u4*4];
                ss += r4[u4].x*r4[u4].x + r4[u4].y*r4[u4].y
                    + r4[u4].z*r4[u4].z + r4[u4].w*r4[u4].w;
            }
            ss += __shfl_xor_sync(0xffffffffu, ss, 1);
            ss += __shfl_xor_sync(0xffffffffu, ss, 2);
            float inv = 1.f/(sqrtf(ss) + 1e-6f);
            size_t tg = t0 + tok;
#pragma unroll
            for (int u4=0;u4<4;u4++){
                float4 v = make_float4(r4[u4].x*inv, r4[u4].y*inv, r4[u4].z*inv, r4[u4].w*inv);
                *(float4*)&out[noff + (tg*Gn+g)*64 + jq*16 + u4*4] = v;
            }
        }
        __syncthreads();
    }

    // ===== w_nov (proj column 256) =====
    if (tid < 128)
        wsm[tid] = post_w[(size_t)g*32896 + (size_t)tid*257 + 256];
    __syncthreads();
    {
        float acc = 0.f;
#pragma unroll
        for (int u=0;u<8;u++){
            float4 xv = *(const float4*)&xs[tok*132 + jq*32 + u*4];
            float4 wv = *(const float4*)&wsm[jq*32 + u*4];
            acc += xv.x*wv.x + xv.y*wv.y + xv.z*wv.z + xv.w*wv.w;
        }
        acc += __shfl_xor_sync(0xffffffffu, acc, 1);
        acc += __shfl_xor_sync(0xffffffffu, acc, 2);
        if (jq == 0){
            size_t tg = t0 + tok;
            float nv = acc + post_b[(size_t)g*257 + 256];
            out[O_WN + tg*Gn + g] = 1.f/(1.f + expf(-nv));
        }
    }
}

extern "C" void kernel_launch(void* const* d_in, const int* in_sizes, int n_in,
                              void* d_out, int out_size) {
    const float* x_col      = (const float*)d_in[0];
    const float* pm_state   = (const float*)d_in[1];
    const float* em_state   = (const float*)d_in[2];
    const float* z_hat_prev = (const float*)d_in[3];
    const float* ffn_norm_w = (const float*)d_in[4];
    const float* ffn_norm_b = (const float*)d_in[5];
    const float* ffn_up_w   = (const float*)d_in[6];
    const float* ffn_up_b   = (const float*)d_in[7];
    const float* ffn_down_w = (const float*)d_in[8];
    const float* ffn_down_b = (const float*)d_in[9];
    const float* pm_up_w    = (const float*)d_in[10];
    const float* pm_up_b    = (const float*)d_in[11];
    const float* pm_down_w  = (const float*)d_in[12];
    const float* pm_down_b  = (const float*)d_in[13];
    const float* em_up_w    = (const float*)d_in[14];
    const float* em_up_b    = (const float*)d_in[15];
    const float* em_down_w  = (const float*)d_in[16];
    const float* em_down_b  = (const float*)d_in[17];
    const float* post_w     = (const float*)d_in[18];
    const float* post_b     = (const float*)d_in[19];
    const float* enc_w      = (const float*)d_in[20];
    const float* enc_b      = (const float*)d_in[21];
    const float* pred_w     = (const float*)d_in[22];
    const float* pred_b     = (const float*)d_in[23];
    const float* gain_w     = (const float*)d_in[24];
    const float* gain_b     = (const float*)d_in[25];
    float* out = (float*)d_out;

    const int smem = (3*64*132 + 2*1024)*4;  // 109568 B
    cudaFuncSetAttribute(ccg_kernel, cudaFuncAttributeMaxDynamicSharedMemorySize, smem);
    dim3 grid(32, 128);
    ccg_kernel<<<grid, 256, smem>>>(
        x_col, pm_state, em_state, z_hat_prev,
        ffn_norm_w, ffn_norm_b, ffn_up_w, ffn_up_b, ffn_down_w, ffn_down_b,
        pm_up_w, pm_up_b, pm_down_w, pm_down_b,
        em_up_w, em_up_b, em_down_w, em_down_b,
        post_w, post_b, enc_w, enc_b, pred_w, pred_b, gain_w, gain_b,
        out);
}

// round 9
// speedup vs baseline: 1.3369x; 1.0039x over previous
#include <cuda_runtime.h>
#include <math.h>

#define Gn 128
typedef unsigned long long U64;

static const long long O_XOUT=0LL, O_Z=33554432LL, O_ZHAT=50331648LL, O_SURP=67108864LL,
 O_KC=67371008LL, O_VP=84148224LL, O_GATE=100925440LL, O_QN=101187584LL,
 O_VC=117964800LL, O_WN=134742016LL, O_S4=135004160LL;

__device__ __forceinline__ void f2fma(U64& d, U64 a, U64 b){
    asm("fma.rn.f32x2 %0, %1, %2, %0;" : "+l"(d) : "l"(a), "l"(b));
}
__device__ __forceinline__ void f2add(U64& d, U64 a){
    asm("add.rn.f32x2 %0, %0, %1;" : "+l"(d) : "l"(a));
}
__device__ __forceinline__ U64 dup2(float a){
    U64 r; asm("mov.b64 %0, {%1, %1};" : "=l"(r) : "f"(a)); return r;
}
__device__ __forceinline__ float4 pk4(U64 p0, U64 p1){
    float4 v;
    asm("mov.b64 {%0, %1}, %2;" : "=f"(v.x), "=f"(v.y) : "l"(p0));
    asm("mov.b64 {%0, %1}, %2;" : "=f"(v.z), "=f"(v.w) : "l"(p1));
    return v;
}
// constant-index select of accumulator pair — NO dynamic register-array indexing
__device__ __forceinline__ float4 pksel(const U64* c, int flag){
    U64 p0 = flag ? c[2] : c[0];
    U64 p1 = flag ? c[3] : c[1];
    return pk4(p0, p1);
}
__device__ __forceinline__ void cpa16(float* dst, const float* src){
    unsigned d = (unsigned)__cvta_generic_to_shared(dst);
    asm volatile("cp.async.ca.shared.global [%0], [%1], 16;" :: "r"(d), "l"(src) : "memory");
}
__device__ __forceinline__ void cpa4(float* dst, const float* src){
    unsigned d = (unsigned)__cvta_generic_to_shared(dst);
    asm volatile("cp.async.ca.shared.global [%0], [%1], 4;" :: "r"(d), "l"(src) : "memory");
}
__device__ __forceinline__ void cpcommit(){ asm volatile("cp.async.commit_group;" ::: "memory"); }
__device__ __forceinline__ void cpwait0(){ asm volatile("cp.async.wait_group 0;" ::: "memory"); }
__device__ __forceinline__ void fz2(U64* c){
#pragma unroll
    for (int i=0;i<32;i++) c[i]=0ULL;
}
__device__ __forceinline__ void redK2(U64* c){
#pragma unroll
    for (int i=0;i<32;i++) f2add(c[i], __shfl_xor_sync(0xffffffffu, c[i], 16));
}
__device__ __forceinline__ void redK4(U64* c){
#pragma unroll
    for (int i=0;i<32;i++){
        f2add(c[i], __shfl_xor_sync(0xffffffffu, c[i], 8));
        f2add(c[i], __shfl_xor_sync(0xffffffffu, c[i], 16));
    }
}

// ---- inner loops: warp = 8 tokens (ty); lanes split K (interleaved, conflict-free) ----
// A addresses per LDS now span 64B (g64) / 32B (g128) across k-split lanes: 1 wavefront.
__device__ __forceinline__ void innU64(const float* As, int kbase, const float* wb, int rbase,
                                       U64 c2[][4], int ty, int tx8){
    float4 a4[8];
#pragma unroll
    for (int tt=0;tt<8;tt++) a4[tt] = *(const float4*)&As[(ty*8+tt)*132 + kbase];
#pragma unroll
    for (int r=0;r<4;r++){
        ulonglong2 w0 = *(const ulonglong2*)&wb[(rbase+r)*64 + tx8*4];
        ulonglong2 w1 = *(const ulonglong2*)&wb[(rbase+r)*64 + 32 + tx8*4];
#pragma unroll
        for (int tt=0;tt<8;tt++){
            U64 a = dup2(((const float*)&a4[tt])[r]);
            f2fma(c2[tt][0],a,w0.x); f2fma(c2[tt][1],a,w0.y);
            f2fma(c2[tt][2],a,w1.x); f2fma(c2[tt][3],a,w1.y);
        }
    }
}
__device__ __forceinline__ void innU128(const float* As, int kbase, const float* wb, int rbase,
                                        U64 c2[][4], int ty, int tx){
#pragma unroll
    for (int rp=0;rp<2;rp++){
        float2 a2[8];
#pragma unroll
        for (int tt=0;tt<8;tt++) a2[tt] = *(const float2*)&As[(ty*8+tt)*132 + kbase + rp*2];
#pragma unroll
        for (int rr=0;rr<2;rr++){
            int r = rp*2+rr;
            ulonglong2 w0 = *(const ulonglong2*)&wb[(rbase+r)*128 + tx*4];
            ulonglong2 w1 = *(const ulonglong2*)&wb[(rbase+r)*128 + 64 + tx*4];
#pragma unroll
            for (int tt=0;tt<8;tt++){
                U64 a = dup2(rr ? a2[tt].y : a2[tt].x);
                f2fma(c2[tt][0],a,w0.x); f2fma(c2[tt][1],a,w0.y);
                f2fma(c2[tt][2],a,w1.x); f2fma(c2[tt][3],a,w1.y);
            }
        }
    }
}

// ---- GEMM drivers: chunk c covers consecutive k; lane kh takes k = 16c/8c + kh*4 + r ----
__device__ __forceinline__ void g64(const float* As, const float* __restrict__ W, long wst, int K,
                                    float* wsm, U64 c2[][4], int ty, int kh2, int tx8, int tid){
    int nc = K>>4;
    int rr = tid>>4, c4 = (tid&15)*4;
    cpa16(&wsm[rr*64+c4], &W[(size_t)rr*wst + c4]); cpcommit();
    for (int c=0;c<nc;c++){
        cpwait0(); __syncthreads();
        if (c+1<nc){
            cpa16(&wsm[((c+1)&1)*1024 + rr*64+c4],
                  &W[(size_t)((c+1)*16 + rr)*wst + c4]); cpcommit();
        }
        innU64(As, c*16 + kh2*4, wsm + (c&1)*1024, kh2*4, c2, ty, tx8);
    }
    __syncthreads();
}
__device__ __forceinline__ void g64T(const float* As, const float* __restrict__ S, int slots,
                                     float* wsm, U64 c2[][4], int ty, int kh2, int tx8, int tid){
    int s = tid&63, q = tid>>6;   // q in 0..3 -> rows q*4..q*4+3 of the 16-row chunk
    for (int c=0;c<4;c++){
        float4 v = make_float4(0.f,0.f,0.f,0.f);
        if (s < slots) v = *(const float4*)&S[s*64 + c*16 + q*4];
        __syncthreads();
        wsm[(q*4+0)*64+s]=v.x; wsm[(q*4+1)*64+s]=v.y;
        wsm[(q*4+2)*64+s]=v.z; wsm[(q*4+3)*64+s]=v.w;
        __syncthreads();
        innU64(As, c*16 + kh2*4, wsm, kh2*4, c2, ty, tx8);
    }
    __syncthreads();
}
template<bool UA>
__device__ __forceinline__ void g128(const float* As, const float* __restrict__ W, long wst, int K,
                                     float* wsm, U64 c2[][4], int ty, int kh, int tx, int tid){
    int nc = K>>3;
    int rr8 = tid>>5, c48 = (tid&31)*4;
#define STAGE128(cc, buf) do { \
    if (UA){ \
        for (int j=0;j<4;j++){ int flat=tid+256*j; int r_=flat>>7, col_=flat&127; \
            cpa4(&(buf)[r_*128+col_], &W[(size_t)((cc)*8 + r_)*wst + col_]); } \
    } else { \
        cpa16(&(buf)[rr8*128+c48], &W[(size_t)((cc)*8 + rr8)*wst + c48]); \
    } \
    cpcommit(); } while(0)
    STAGE128(0, wsm);
    for (int c=0;c<nc;c++){
        cpwait0(); __syncthreads();
        if (c+1<nc) STAGE128(c+1, wsm + ((c+1)&1)*1024);
        innU128(As, c*8 + kh*4, wsm + (c&1)*1024, kh*4, c2, ty, tx);
    }
    __syncthreads();
#undef STAGE128
}

// ---- epilogues (all constant-index accumulator access) ----
__device__ __forceinline__ void eps64(U64 c2[][4], float* buf, const float* bias,
                                      int ty, int kh2, int tx8){
    if (kh2 >= 2) return;
    int col = kh2*32 + tx8*4;
    float4 bv = bias ? *(const float4*)&bias[col] : make_float4(0.f,0.f,0.f,0.f);
#pragma unroll
    for (int tt=0;tt<8;tt++){
        float4 v = pksel(c2[tt], kh2);
        v.x+=bv.x; v.y+=bv.y; v.z+=bv.z; v.w+=bv.w;
        *(float4*)&buf[(ty*8+tt)*132 + col] = v;
    }
}
__device__ __forceinline__ void epxs(U64 c2[][4], float* xs, int ty, int kh, int tx){
    int col = kh*64 + tx*4;
#pragma unroll
    for (int tt=0;tt<8;tt++){
        float* p = &xs[(ty*8+tt)*132 + col];
        float4 x = *(float4*)p;
        float4 v = pksel(c2[tt], kh);
        x.x+=v.x; x.y+=v.y; x.z+=v.z; x.w+=v.w;
        *(float4*)p = x;
    }
}

template <int SLOTS>
__device__ __forceinline__ void softmax_q(float* buf, int tok, int jq){
    const int nS = SLOTS/4;
    float l[nS]; float m = -1e30f;
#pragma unroll
    for (int i=0;i<nS;i++){ l[i] = buf[tok*132 + jq*nS + i]*0.125f; m = fmaxf(m, l[i]); }
    m = fmaxf(m, __shfl_xor_sync(0xffffffffu, m, 1));
    m = fmaxf(m, __shfl_xor_sync(0xffffffffu, m, 2));
    float s = 0.f;
#pragma unroll
    for (int i=0;i<nS;i++){ l[i]=expf(l[i]-m); s+=l[i]; }
    s += __shfl_xor_sync(0xffffffffu, s, 1);
    s += __shfl_xor_sync(0xffffffffu, s, 2);
    float inv = 1.f/s;
#pragma unroll
    for (int i=0;i<nS;i++) buf[tok*132 + jq*nS + i] = l[i]*inv;
}

__global__ void __launch_bounds__(256, 2)
ccg_kernel(
    const float* __restrict__ x_col, const float* __restrict__ pm_state,
    const float* __restrict__ em_state, const float* __restrict__ z_hat_prev,
    const float* __restrict__ ffn_norm_w, const float* __restrict__ ffn_norm_b,
    const float* __restrict__ ffn_up_w, const float* __restrict__ ffn_up_b,
    const float* __restrict__ ffn_down_w, const float* __restrict__ ffn_down_b,
    const float* __restrict__ pm_up_w, const float* __restrict__ pm_up_b,
    const float* __restrict__ pm_down_w, const float* __restrict__ pm_down_b,
    const float* __restrict__ em_up_w, const float* __restrict__ em_up_b,
    const float* __restrict__ em_down_w, const float* __restrict__ em_down_b,
    const float* __restrict__ post_w, const float* __restrict__ post_b,
    const float* __restrict__ enc_w, const float* __restrict__ enc_b,
    const float* __restrict__ pred_w, const float* __restrict__ pred_b,
    const float* __restrict__ gain_w, const float* __restrict__ gain_b,
    float* __restrict__ out)
{
    extern __shared__ float smf[];
    float* xs  = smf;               // 64 x 132 residual
    float* hs  = xs + 64*132;       // 64 x 132 logits/z/gain/gelu/post-k
    float* bC  = hs + 64*132;       // 64 x 132 q/apply/delta/h
    float* wsm = bC + 64*132;       // 2 x 1024 weight staging

    const int tid = threadIdx.x;
    const int lane = tid & 31, ty = tid >> 5;
    const int kh = lane >> 4, tx = lane & 15;
    const int kh2 = lane >> 3, tx8 = lane & 7;
    const int tok = tid >> 2, jq = tid & 3;
    const int g = blockIdx.y, t0 = blockIdx.x*64;
    const int bs = t0 >> 9, bidx = g >> 4;

    U64 c2[8][4];

#pragma unroll
    for (int jj=0;jj<8;jj++){
        int flat = tid + 256*jj, r = flat>>5, c4 = flat&31;
        *(float4*)&xs[r*132 + c4*4] =
            *(const float4*)&x_col[((size_t)(t0+r)*Gn + g)*128 + c4*4];
    }

    // ===== pm stage =====
    fz2(&c2[0][0]);
    g64(xs, pm_up_w + (size_t)g*8192, 64, 128, wsm, c2, ty, kh2, tx8, tid);
    redK4(&c2[0][0]);
    eps64(c2, bC, pm_up_b + g*64, ty, kh2, tx8);

    const float* Spm = pm_state + (size_t)((bs*8 + bidx)*16)*64;
    fz2(&c2[0][0]);
    g64T(bC, Spm, 16, wsm, c2, ty, kh2, tx8, tid);
    redK4(&c2[0][0]);
    eps64(c2, hs, (const float*)0, ty, kh2, tx8);
    __syncthreads();
    softmax_q<16>(hs, tok, jq);
    __syncthreads();

    fz2(&c2[0][0]);
    g64(hs, Spm, 64, 16, wsm, c2, ty, kh2, tx8, tid);
    redK4(&c2[0][0]);
    eps64(c2, bC, (const float*)0, ty, kh2, tx8);

    fz2(&c2[0][0]);
    g128<false>(bC, pm_down_w + (size_t)g*8192, 128, 64, wsm, c2, ty, kh, tx, tid);
    redK2(&c2[0][0]);
    {   int col = kh*64 + tx*4;
        float4 bv = *(const float4*)&pm_down_b[g*128 + col];
#pragma unroll
        for (int tt=0;tt<8;tt++){
            float* p = &xs[(ty*8+tt)*132 + col];
            float4 x = *(float4*)p; float4 v = pksel(c2[tt], kh);
            x.x+=v.x+bv.x; x.y+=v.y+bv.y; x.z+=v.z+bv.z; x.w+=v.w+bv.w;
            *(float4*)p = x;
        }
    }

    // ===== em stage =====
    fz2(&c2[0][0]);
    g64(xs, em_up_w + (size_t)g*8192, 64, 128, wsm, c2, ty, kh2, tx8, tid);
    redK4(&c2[0][0]);
    eps64(c2, bC, em_up_b + g*64, ty, kh2, tx8);

    const float* Sem = em_state + (size_t)((bs*8 + bidx)*64)*64;
    fz2(&c2[0][0]);
    g64T(bC, Sem, 64, wsm, c2, ty, kh2, tx8, tid);
    redK4(&c2[0][0]);
    eps64(c2, hs, (const float*)0, ty, kh2, tx8);
    __syncthreads();
    softmax_q<64>(hs, tok, jq);
    __syncthreads();

    fz2(&c2[0][0]);
    g64(hs, Sem, 64, 64, wsm, c2, ty, kh2, tx8, tid);
    redK4(&c2[0][0]);
    eps64(c2, bC, (const float*)0, ty, kh2, tx8);

    fz2(&c2[0][0]);
    g128<false>(bC, em_down_w + (size_t)g*8192, 128, 64, wsm, c2, ty, kh, tx, tid);
    redK2(&c2[0][0]);
    {   int col = kh*64 + tx*4;
        float4 bv = *(const float4*)&em_down_b[g*128 + col];
#pragma unroll
        for (int tt=0;tt<8;tt++){
            float* p = &xs[(ty*8+tt)*132 + col];
            float4 x = *(float4*)p; float4 v = pksel(c2[tt], kh);
            x.x+=v.x+bv.x; x.y+=v.y+bv.y; x.z+=v.z+bv.z; x.w+=v.w+bv.w;
            *(float4*)p = x;
        }
    }

    // ===== enc / delta / surprise =====
    fz2(&c2[0][0]);
    g64(xs, enc_w + (size_t)g*8192, 64, 128, wsm, c2, ty, kh2, tx8, tid);
    redK4(&c2[0][0]);
    if (kh2 == 0){
        float ss[8];
        float4 b0 = *(const float4*)&enc_b[g*64 + tx8*4];
        float4 b1 = *(const float4*)&enc_b[g*64 + 32 + tx8*4];
#pragma unroll
        for (int tt=0;tt<8;tt++){
            int t = ty*8+tt; size_t tg = t0+t;
            float4 z0 = pk4(c2[tt][0], c2[tt][1]);
            float4 z1 = pk4(c2[tt][2], c2[tt][3]);
            z0.x+=b0.x; z0.y+=b0.y; z0.z+=b0.z; z0.w+=b0.w;
            z1.x+=b1.x; z1.y+=b1.y; z1.z+=b1.z; z1.w+=b1.w;
            float4 h0 = *(const float4*)&z_hat_prev[(tg*Gn+g)*64 + tx8*4];
            float4 h1 = *(const float4*)&z_hat_prev[(tg*Gn+g)*64 + 32 + tx8*4];
            float4 d0 = make_float4(z0.x-h0.x, z0.y-h0.y, z0.z-h0.z, z0.w-h0.w);
            float4 d1 = make_float4(z1.x-h1.x, z1.y-h1.y, z1.z-h1.z, z1.w-h1.w);
            ss[tt] = d0.x*d0.x+d0.y*d0.y+d0.z*d0.z+d0.w*d0.w
                   + d1.x*d1.x+d1.y*d1.y+d1.z*d1.z+d1.w*d1.w;
            *(float4*)&hs[t*132 + tx8*4] = z0;      *(float4*)&hs[t*132 + 32 + tx8*4] = z1;
            *(float4*)&bC[t*132 + tx8*4] = d0;      *(float4*)&bC[t*132 + 32 + tx8*4] = d1;
            *(float4*)&out[O_Z + (tg*Gn+g)*64 + tx8*4] = z0;
            *(float4*)&out[O_Z + (tg*Gn+g)*64 + 32 + tx8*4] = z1;
        }
#pragma unroll
        for (int tt=0;tt<8;tt++){
            ss[tt] += __shfl_xor_sync(0x000000ffu, ss[tt], 1);
            ss[tt] += __shfl_xor_sync(0x000000ffu, ss[tt], 2);
            ss[tt] += __shfl_xor_sync(0x000000ffu, ss[tt], 4);
        }
        if (tx8 == 0){
#pragma unroll
            for (int tt=0;tt<8;tt++){
                size_t tg = t0 + ty*8 + tt;
                float s = sqrtf(ss[tt]);
                out[O_SURP + tg*Gn + g] = s;
                out[O_S4 + tg*Gn + g] = s;
                out[O_GATE + tg*Gn + g] = fminf(s, 1.f);
            }
        }
    }
    __syncthreads();

    // ===== z_hat (z in hs) =====
    fz2(&c2[0][0]);
    g64(hs, pred_w + (size_t)g*4096, 64, 64, wsm, c2, ty, kh2, tx8, tid);
    redK4(&c2[0][0]);
    if (kh2 < 2){
        int col = kh2*32 + tx8*4;
        float4 bv = *(const float4*)&pred_b[g*64 + col];
#pragma unroll
        for (int tt=0;tt<8;tt++){
            size_t tg = t0 + ty*8 + tt;
            float4 v = pksel(c2[tt], kh2);
            v.x+=bv.x; v.y+=bv.y; v.z+=bv.z; v.w+=bv.w;
            *(float4*)&out[O_ZHAT + (tg*Gn+g)*64 + col] = v;
        }
    }

    // ===== gain (delta in bC) -> hs =====
    fz2(&c2[0][0]);
    g128<false>(bC, gain_w + (size_t)g*8192, 128, 64, wsm, c2, ty, kh, tx, tid);
    redK2(&c2[0][0]);
    {   int col = kh*64 + tx*4;
        float4 bv = *(const float4*)&gain_b[g*128 + col];
#pragma unroll
        for (int tt=0;tt<8;tt++){
            float4 v = pksel(c2[tt], kh);
            float4 o;
            o.x = 1.f + 0.1f*tanhf(v.x+bv.x); o.y = 1.f + 0.1f*tanhf(v.y+bv.y);
            o.z = 1.f + 0.1f*tanhf(v.z+bv.z); o.w = 1.f + 0.1f*tanhf(v.w+bv.w);
            *(float4*)&hs[(ty*8+tt)*132 + col] = o;
        }
    }
    __syncthreads();

    // ===== layernorm * gain -> bC =====
    {
        float s=0.f, sq=0.f; float4 xv[8];
#pragma unroll
        for (int u=0;u<8;u++){
            xv[u] = *(const float4*)&xs[tok*132 + jq*32 + u*4];
            s  += xv[u].x+xv[u].y+xv[u].z+xv[u].w;
            sq += xv[u].x*xv[u].x+xv[u].y*xv[u].y+xv[u].z*xv[u].z+xv[u].w*xv[u].w;
        }
        s  += __shfl_xor_sync(0xffffffffu, s, 1);
        s  += __shfl_xor_sync(0xffffffffu, s, 2);
        sq += __shfl_xor_sync(0xffffffffu, sq, 1);
        sq += __shfl_xor_sync(0xffffffffu, sq, 2);
        float mu = s*(1.f/128.f);
        float rstd = rsqrtf(sq*(1.f/128.f) - mu*mu + 1e-5f);
#pragma unroll
        for (int u=0;u<8;u++){
            int cb = jq*32 + u*4;
            float4 w4 = *(const float4*)&ffn_norm_w[g*128 + cb];
            float4 b4 = *(const float4*)&ffn_norm_b[g*128 + cb];
            float4 g4 = *(const float4*)&hs[tok*132 + cb];
            float4 h4;
            h4.x = ((xv[u].x-mu)*rstd*w4.x + b4.x)*g4.x;
            h4.y = ((xv[u].y-mu)*rstd*w4.y + b4.y)*g4.y;
            h4.z = ((xv[u].z-mu)*rstd*w4.z + b4.z)*g4.z;
            h4.w = ((xv[u].w-mu)*rstd*w4.w + b4.w)*g4.w;
            *(float4*)&bC[tok*132 + cb] = h4;
        }
    }

    // ===== FFN: h in bC; gelu -> hs; down accumulates into xs =====
    for (int ch=0; ch<4; ch++){
        fz2(&c2[0][0]);
        g128<false>(bC, ffn_up_w + (size_t)g*65536 + ch*128, 512, 128, wsm, c2, ty, kh, tx, tid);
        redK2(&c2[0][0]);
        {   int col = kh*64 + tx*4;
            float4 bv = *(const float4*)&ffn_up_b[g*512 + ch*128 + col];
#pragma unroll
            for (int tt=0;tt<8;tt++){
                float4 v = pksel(c2[tt], kh);
                float4 o;
                float u0=v.x+bv.x, u1=v.y+bv.y, u2=v.z+bv.z, u3=v.w+bv.w;
                o.x = 0.5f*u0*(1.f+erff(u0*0.70710678f));
                o.y = 0.5f*u1*(1.f+erff(u1*0.70710678f));
                o.z = 0.5f*u2*(1.f+erff(u2*0.70710678f));
                o.w = 0.5f*u3*(1.f+erff(u3*0.70710678f));
                *(float4*)&hs[(ty*8+tt)*132 + col] = o;
            }
        }
        fz2(&c2[0][0]);
        g128<false>(hs, ffn_down_w + (size_t)g*65536 + (size_t)ch*128*128, 128, 128, wsm, c2, ty, kh, tx, tid);
        redK2(&c2[0][0]);
        epxs(c2, xs, ty, kh, tx);
    }

    // ===== x_out: add down-bias, store =====
    {   int col = kh*64 + tx*4;
        float4 bv = *(const float4*)&ffn_down_b[g*128 + col];
#pragma unroll
        for (int tt=0;tt<8;tt++){
            int t = ty*8+tt; size_t tg = t0+t;
            float* p = &xs[t*132 + col];
            float4 x = *(float4*)p;
            x.x+=bv.x; x.y+=bv.y; x.z+=bv.z; x.w+=bv.w;
            *(float4*)p = x;
            *(float4*)&out[O_XOUT + (tg*Gn+g)*128 + col] = x;
        }
    }

    // ===== post projection: two 128-wide passes over xs =====
    for (int ph=0; ph<2; ph++){
        fz2(&c2[0][0]);
        g128<true>(xs, post_w + (size_t)g*32896 + ph*128, 257, 128, wsm, c2, ty, kh, tx, tid);
        redK2(&c2[0][0]);
        long long voff = ph ? O_VC : O_VP;
        long long noff = ph ? O_QN : O_KC;
        {   int col = kh*64 + tx*4;
            const float* pb = &post_b[(size_t)g*257 + ph*128 + col];   // stride 257: scalar loads
            float4 bv = make_float4(pb[0], pb[1], pb[2], pb[3]);
#pragma unroll
            for (int tt=0;tt<8;tt++){
                size_t tg = t0 + ty*8 + tt;
                float4 v = pksel(c2[tt], kh);
                v.x+=bv.x; v.y+=bv.y; v.z+=bv.z; v.w+=bv.w;
                if (kh == 0) *(float4*)&hs[(ty*8+tt)*132 + tx*4] = v;
                else *(float4*)&out[voff + (tg*Gn+g)*64 + tx*4] = v;
            }
        }
        __syncthreads();
        {   // normalize hs rows (64 cols) -> out[noff]
            float4 r4[4]; float ss = 0.f;
#pragma unroll
            for (int u4=0;u4<4;u4++){
                r4[u4] = *(const float4*)&hs[tok*132 + jq*16 + u4*4];
                ss += r4[u4].x*r4[u4].x + r4[u4].y*r4[u4].y
                    + r4[u4].z*r4[u4].z + r4[u4].w*r4[u4].w;
            }
            ss += __shfl_xor_sync(0xffffffffu, ss, 1);
            ss += __shfl_xor_sync(0xffffffffu, ss, 2);
            float inv = 1.f/(sqrtf(ss) + 1e-6f);
            size_t tg = t0 + tok;
#pragma unroll
            for (int u4=0;u4<4;u4++){
                float4 v = make_float4(r4[u4].x*inv, r4[u4].y*inv, r4[u4].z*inv, r4[u4].w*inv);
                *(float4*)&out[noff + (tg*Gn+g)*64 + jq*16 + u4*4] = v;
            }
        }
        __syncthreads();
    }

    // ===== w_nov (proj column 256) =====
    if (tid < 128)
        wsm[tid] = post_w[(size_t)g*32896 + (size_t)tid*257 + 256];
    __syncthreads();
    {
        float acc = 0.f;
#pragma unroll
        for (int u=0;u<8;u++){
            float4 xv = *(const float4*)&xs[tok*132 + jq*32 + u*4];
            float4 wv = *(const float4*)&wsm[jq*32 + u*4];
            acc += xv.x*wv.x + xv.y*wv.y + xv.z*wv.z + xv.w*wv.w;
        }
        acc += __shfl_xor_sync(0xffffffffu, acc, 1);
        acc += __shfl_xor_sync(0xffffffffu, acc, 2);
        if (jq == 0){
            size_t tg = t0 + tok;
            float nv = acc + post_b[(size_t)g*257 + 256];
            out[O_WN + tg*Gn + g] = 1.f/(1.f + expf(-nv));
        }
    }
}

extern "C" void kernel_launch(void* const* d_in, const int* in_sizes, int n_in,
                              void* d_out, int out_size) {
    const float* x_col      = (const float*)d_in[0];
    const float* pm_state   = (const float*)d_in[1];
    const float* em_state   = (const float*)d_in[2];
    const float* z_hat_prev = (const float*)d_in[3];
    const float* ffn_norm_w = (const float*)d_in[4];
    const float* ffn_norm_b = (const float*)d_in[5];
    const float* ffn_up_w   = (const float*)d_in[6];
    const float* ffn_up_b   = (const float*)d_in[7];
    const float* ffn_down_w = (const float*)d_in[8];
    const float* ffn_down_b = (const float*)d_in[9];
    const float* pm_up_w    = (const float*)d_in[10];
    const float* pm_up_b    = (const float*)d_in[11];
    const float* pm_down_w  = (const float*)d_in[12];
    const float* pm_down_b  = (const float*)d_in[13];
    const float* em_up_w    = (const float*)d_in[14];
    const float* em_up_b    = (const float*)d_in[15];
    const float* em_down_w  = (const float*)d_in[16];
    const float* em_down_b  = (const float*)d_in[17];
    const float* post_w     = (const float*)d_in[18];
    const float* post_b     = (const float*)d_in[19];
    const float* enc_w      = (const float*)d_in[20];
    const float* enc_b      = (const float*)d_in[21];
    const float* pred_w     = (const float*)d_in[22];
    const float* pred_b     = (const float*)d_in[23];
    const float* gain_w     = (const float*)d_in[24];
    const float* gain_b     = (const float*)d_in[25];
    float* out = (float*)d_out;

    const int smem = (3*64*132 + 2*1024)*4;  // 109568 B
    cudaFuncSetAttribute(ccg_kernel, cudaFuncAttributeMaxDynamicSharedMemorySize, smem);
    dim3 grid(32, 128);
    ccg_kernel<<<grid, 256, smem>>>(
        x_col, pm_state, em_state, z_hat_prev,
        ffn_norm_w, ffn_norm_b, ffn_up_w, ffn_up_b, ffn_down_w, ffn_down_b,
        pm_up_w, pm_up_b, pm_down_w, pm_down_b,
        em_up_w, em_up_b, em_down_w, em_down_b,
        post_w, post_b, enc_w, enc_b, pred_w, pred_b, gain_w, gain_b,
        out);
}